// round 8
// baseline (speedup 1.0000x reference)
#include <cuda_runtime.h>

#define N_NODES 50000
#define N_EDGES 800000
#define DCH 64
#define NEG_SLOPE 0.2f
#define LN_EPS 1e-5f

// ---------------- scratch (no allocs allowed) ----------------
__device__ float g_xl[N_NODES * DCH];      // xl = x@Wl + bl
__device__ float g_xr[N_NODES * DCH];      // xr = x@Wr + br
__device__ int   g_cnt[N_NODES];           // per-dst edge counts
__device__ int   g_off[N_NODES + 1];       // CSR offsets
__device__ int   g_wp[N_NODES];            // scatter write pointers
__device__ int   g_bsum[64];               // scan block sums
__device__ int   g_ssrc[N_EDGES];          // src ids grouped by dst

// ---------------- K0: zero counters ----------------
__global__ void zero_kernel() {
    int i = blockIdx.x * blockDim.x + threadIdx.x;
    if (i < N_NODES) g_cnt[i] = 0;
    if (i == 0) g_off[0] = 0;
}

// ---------------- K1: count edges per dst ----------------
__global__ __launch_bounds__(256) void count_kernel(const int* __restrict__ ei) {
    int e = blockIdx.x * 256 + threadIdx.x;   // grid covers N_EDGES exactly
    atomicAdd(&g_cnt[__ldg(&ei[N_EDGES + e])], 1);
}

// ---------------- K2a: per-block inclusive scan (1024/block, 49 blocks) ----------------
__global__ __launch_bounds__(1024) void scan1_kernel() {
    __shared__ int wsum[32];
    const int tid = threadIdx.x, lane = tid & 31, wid = tid >> 5;
    const int i = blockIdx.x * 1024 + tid;
    int v = (i < N_NODES) ? g_cnt[i] : 0;
    int xv = v;
#pragma unroll
    for (int d = 1; d < 32; d <<= 1) {
        int t = __shfl_up_sync(0xffffffffu, xv, d);
        if (lane >= d) xv += t;
    }
    if (lane == 31) wsum[wid] = xv;
    __syncthreads();
    if (wid == 0) {
        int s = wsum[lane];
#pragma unroll
        for (int d = 1; d < 32; d <<= 1) {
            int t = __shfl_up_sync(0xffffffffu, s, d);
            if (lane >= d) s += t;
        }
        wsum[lane] = s;
    }
    __syncthreads();
    int incl = xv + (wid > 0 ? wsum[wid - 1] : 0);
    if (i < N_NODES) g_off[i + 1] = incl;
    if (tid == 1023) g_bsum[blockIdx.x] = incl;
}

// ---------------- K2b: add block prefixes, build write pointers ----------------
__global__ __launch_bounds__(1024) void scan2_kernel() {
    __shared__ int spref;
    const int tid = threadIdx.x;
    if (tid == 0) {
        int p = 0;
        for (int b = 0; b < (int)blockIdx.x; b++) p += g_bsum[b];
        spref = p;
    }
    __syncthreads();
    const int i = blockIdx.x * 1024 + tid;
    if (i < N_NODES) {
        int incl = g_off[i + 1] + spref;
        g_off[i + 1] = incl;
        g_wp[i] = incl - g_cnt[i];   // exclusive prefix
    }
}

// ---------------- K3: scatter edges into dst-grouped order ----------------
__global__ __launch_bounds__(256) void scatter_kernel(const int* __restrict__ ei) {
    int e = blockIdx.x * 256 + threadIdx.x;
    int src = __ldg(&ei[e]);
    int dst = __ldg(&ei[N_EDGES + e]);
    int pos = atomicAdd(&g_wp[dst], 1);
    g_ssrc[pos] = src;
}

// ---------------- K4: fused dual GEMM ----------------
#define GEMM_TILE 128
#define XT_STRIDE 132

__global__ __launch_bounds__(512, 2) void gemm_kernel(
    const float* __restrict__ x,
    const float* __restrict__ Wl, const float* __restrict__ bl,
    const float* __restrict__ Wr, const float* __restrict__ br)
{
    extern __shared__ __align__(16) float smem[];
    float* xT  = smem;                     // 64*132 floats
    float* Wls = smem + 64 * XT_STRIDE;    // 4096
    float* Wrs = Wls + 4096;               // 4096

    const int tid = threadIdx.x;
    const int node0 = blockIdx.x * GEMM_TILE;

#pragma unroll
    for (int i = tid; i < 1024; i += 512) {
        ((float4*)Wls)[i] = __ldg(&((const float4*)Wl)[i]);
        ((float4*)Wrs)[i] = __ldg(&((const float4*)Wr)[i]);
    }
    for (int i4 = tid; i4 < GEMM_TILE * 16; i4 += 512) {
        int nl = i4 >> 4;
        int k4 = (i4 & 15) * 4;
        int n = node0 + nl;
        float4 v = (n < N_NODES) ? ((const float4*)x)[(size_t)n * 16 + (i4 & 15)]
                                 : make_float4(0.f, 0.f, 0.f, 0.f);
        xT[(k4 + 0) * XT_STRIDE + nl] = v.x;
        xT[(k4 + 1) * XT_STRIDE + nl] = v.y;
        xT[(k4 + 2) * XT_STRIDE + nl] = v.z;
        xT[(k4 + 3) * XT_STRIDE + nl] = v.w;
    }
    __syncthreads();

    const int dq = (tid & 15) * 4;
    const int nq = (tid >> 4) * 4;

    float accl[4][4] = {{0.f}}, accr[4][4] = {{0.f}};

#pragma unroll 4
    for (int k = 0; k < 64; k++) {
        float4 xv = *(const float4*)&xT[k * XT_STRIDE + nq];
        float4 wl = *(const float4*)&Wls[k * 64 + dq];
        float4 wr = *(const float4*)&Wrs[k * 64 + dq];
        float xa[4] = {xv.x, xv.y, xv.z, xv.w};
        float wla[4] = {wl.x, wl.y, wl.z, wl.w};
        float wra[4] = {wr.x, wr.y, wr.z, wr.w};
#pragma unroll
        for (int i = 0; i < 4; i++)
#pragma unroll
            for (int j = 0; j < 4; j++) {
                accl[i][j] = fmaf(xa[i], wla[j], accl[i][j]);
                accr[i][j] = fmaf(xa[i], wra[j], accr[i][j]);
            }
    }

    float4 blv = *(const float4*)&bl[dq];
    float4 brv = *(const float4*)&br[dq];
    float bla[4] = {blv.x, blv.y, blv.z, blv.w};
    float bra[4] = {brv.x, brv.y, brv.z, brv.w};

#pragma unroll
    for (int i = 0; i < 4; i++) {
        int n = node0 + nq + i;
        if (n < N_NODES) {
            float4 ol, orr;
            ol.x = accl[i][0] + bla[0]; ol.y = accl[i][1] + bla[1];
            ol.z = accl[i][2] + bla[2]; ol.w = accl[i][3] + bla[3];
            orr.x = accr[i][0] + bra[0]; orr.y = accr[i][1] + bra[1];
            orr.z = accr[i][2] + bra[2]; orr.w = accr[i][3] + bra[3];
            *(float4*)&g_xl[(size_t)n * 64 + dq] = ol;
            *(float4*)&g_xr[(size_t)n * 64 + dq] = orr;
        }
    }
}

__device__ __forceinline__ float lrelu(float v) {
    return v > 0.f ? v : NEG_SLOPE * v;
}

// ---------------- K5: warp-per-dst aggregate + normalize + residual + LN + ELU ----------------
// Warp owns node n. Two 16-lane halves process 2 edges/iter; each of 16 lanes
// holds 4 channels (float4). Registers accumulate sum(p*xl[src]) and sum(p);
// no atomics, no intermediate global arrays. grid = N_NODES/8 = 6250.
__global__ __launch_bounds__(256) void agg_kernel(
    const float* __restrict__ x, const float* __restrict__ att,
    const float* __restrict__ bias, const float* __restrict__ gamma,
    const float* __restrict__ beta, float* __restrict__ out)
{
    const int tid = threadIdx.x;
    const int lane = tid & 31;
    const int half = lane >> 4;
    const int l16 = lane & 15;
    const int n = blockIdx.x * 8 + (tid >> 5);

    const int start = __ldg(&g_off[n]);
    const int deg = __ldg(&g_off[n + 1]) - start;

    const float4 xr = ((const float4*)g_xr)[(size_t)n * 16 + l16];
    const float4 av = __ldg(&((const float4*)att)[l16]);

    float4 acc = make_float4(0.f, 0.f, 0.f, 0.f);
    float den = 0.f;

    const int trips = (deg + 1) >> 1;
    for (int j = 0; j < trips; j++) {
        int i = start + j * 2 + half;
        bool valid = (i < start + deg);
        int idx = valid ? i : start;          // deg >= 1 whenever trips >= 1
        int src = __ldg(&g_ssrc[idx]);
        float4 a = *(const float4*)&g_xl[(size_t)src * 64 + l16 * 4];

        float s = lrelu(a.x + xr.x) * av.x + lrelu(a.y + xr.y) * av.y +
                  lrelu(a.z + xr.z) * av.z + lrelu(a.w + xr.w) * av.w;
        s += __shfl_xor_sync(0xffffffffu, s, 1);   // quad reduce -> head sum
        s += __shfl_xor_sync(0xffffffffu, s, 2);

        float p = valid ? __expf(s) : 0.f;
        acc.x = fmaf(p, a.x, acc.x);
        acc.y = fmaf(p, a.y, acc.y);
        acc.z = fmaf(p, a.z, acc.z);
        acc.w = fmaf(p, a.w, acc.w);
        den += p;
    }

    // combine the two halves (lane i += lane i+16)
    acc.x += __shfl_down_sync(0xffffffffu, acc.x, 16);
    acc.y += __shfl_down_sync(0xffffffffu, acc.y, 16);
    acc.z += __shfl_down_sync(0xffffffffu, acc.z, 16);
    acc.w += __shfl_down_sync(0xffffffffu, acc.w, 16);
    den   += __shfl_down_sync(0xffffffffu, den, 16);

    float inv_den = (den > 0.f) ? __fdividef(1.f, den) : 0.f;

    float4 xv = ((const float4*)x)[(size_t)n * 16 + l16];
    float4 bv = __ldg(&((const float4*)bias)[l16]);

    float c0 = fmaf(acc.x, inv_den, xv.x + bv.x);
    float c1 = fmaf(acc.y, inv_den, xv.y + bv.y);
    float c2 = fmaf(acc.z, inv_den, xv.z + bv.z);
    float c3 = fmaf(acc.w, inv_den, xv.w + bv.w);

    float sum = c0 + c1 + c2 + c3;
    float sq = c0 * c0 + c1 * c1 + c2 * c2 + c3 * c3;
#pragma unroll
    for (int off = 8; off > 0; off >>= 1) {   // stays within each 16-lane half
        sum += __shfl_xor_sync(0xffffffffu, sum, off);
        sq  += __shfl_xor_sync(0xffffffffu, sq, off);
    }
    float mean = sum * (1.f / 64.f);
    float var = sq * (1.f / 64.f) - mean * mean;
    float inv = rsqrtf(var + LN_EPS);

    float4 gv = __ldg(&((const float4*)gamma)[l16]);
    float4 be = __ldg(&((const float4*)beta)[l16]);

    float y0 = (c0 - mean) * inv * gv.x + be.x;
    float y1 = (c1 - mean) * inv * gv.y + be.y;
    float y2 = (c2 - mean) * inv * gv.z + be.z;
    float y3 = (c3 - mean) * inv * gv.w + be.w;
    y0 = y0 > 0.f ? y0 : expm1f(y0);
    y1 = y1 > 0.f ? y1 : expm1f(y1);
    y2 = y2 > 0.f ? y2 : expm1f(y2);
    y3 = y3 > 0.f ? y3 : expm1f(y3);

    if (half == 0) {
        float4 r; r.x = y0; r.y = y1; r.z = y2; r.w = y3;
        ((float4*)out)[(size_t)n * 16 + l16] = r;
    }
}

// ---------------- launch ----------------
#define GEMM_SMEM (64 * XT_STRIDE * 4 + 2 * 4096 * 4)   // 66560 B
#define SCAN_BLOCKS ((N_NODES + 1023) / 1024)            // 49

extern "C" void kernel_launch(void* const* d_in, const int* in_sizes, int n_in,
                              void* d_out, int out_size)
{
    const float* x     = (const float*)d_in[0];
    const int*   ei    = (const int*)d_in[1];
    const float* Wl    = (const float*)d_in[2];
    const float* bl    = (const float*)d_in[3];
    const float* Wr    = (const float*)d_in[4];
    const float* br    = (const float*)d_in[5];
    const float* att   = (const float*)d_in[6];
    const float* bias  = (const float*)d_in[7];
    const float* gamma = (const float*)d_in[8];
    const float* beta  = (const float*)d_in[9];
    float* out = (float*)d_out;

    cudaFuncSetAttribute(gemm_kernel,
                         cudaFuncAttributeMaxDynamicSharedMemorySize, GEMM_SMEM);

    zero_kernel<<<(N_NODES + 255) / 256, 256>>>();
    count_kernel<<<N_EDGES / 256, 256>>>(ei);
    scan1_kernel<<<SCAN_BLOCKS, 1024>>>();
    scan2_kernel<<<SCAN_BLOCKS, 1024>>>();
    scatter_kernel<<<N_EDGES / 256, 256>>>(ei);
    gemm_kernel<<<(N_NODES + GEMM_TILE - 1) / GEMM_TILE, 512, GEMM_SMEM>>>(
        x, Wl, bl, Wr, br);
    agg_kernel<<<N_NODES / 8, 256>>>(x, att, bias, gamma, beta, out);
}

// round 9
// speedup vs baseline: 1.1667x; 1.1667x over previous
#include <cuda_runtime.h>

#define N_NODES 50000
#define N_EDGES 800000
#define DCH 64
#define NEG_SLOPE 0.2f
#define LN_EPS 1e-5f

// ---------------- scratch (no allocs allowed) ----------------
__device__ float g_xl[N_NODES * DCH];      // xl = x@Wl + bl
__device__ float g_xr[N_NODES * DCH];      // xr = x@Wr + br
__device__ float g_denom[N_NODES * 4];     // softmax denominators
__device__ float g_agg[N_NODES * DCH];     // unnormalized aggregated messages

// ---------------- K1: fused dual GEMM + scratch zeroing ----------------
// 512 threads, 128-node tile, dynamic smem (66.5 KB).
// Each thread: 4 nodes x 4 cols x both matrices = 32 accumulators.
#define GEMM_TILE 128
#define XT_STRIDE 132

__global__ __launch_bounds__(512, 2) void gemm_kernel(
    const float* __restrict__ x,
    const float* __restrict__ Wl, const float* __restrict__ bl,
    const float* __restrict__ Wr, const float* __restrict__ br)
{
    extern __shared__ __align__(16) float smem[];
    float* xT  = smem;                     // 64*132 floats
    float* Wls = smem + 64 * XT_STRIDE;    // 4096
    float* Wrs = Wls + 4096;               // 4096

    const int tid = threadIdx.x;
    const int node0 = blockIdx.x * GEMM_TILE;

    // ---- zero this tile's g_agg / g_denom (overlaps with staging) ----
    {
        const float4 z4 = make_float4(0.f, 0.f, 0.f, 0.f);
#pragma unroll
        for (int i = 0; i < 4; i++) {
            int q = tid + i * 512;
            int n = node0 + (q >> 4);
            if (n < N_NODES)
                ((float4*)g_agg)[(size_t)node0 * 16 + q] = z4;
        }
        int n = node0 + (tid >> 2);
        if (n < N_NODES) g_denom[node0 * 4 + tid] = 0.f;
    }

    // ---- stage W (float4, coalesced) ----
#pragma unroll
    for (int i = tid; i < 1024; i += 512) {
        ((float4*)Wls)[i] = __ldg(&((const float4*)Wl)[i]);
        ((float4*)Wrs)[i] = __ldg(&((const float4*)Wr)[i]);
    }

    // ---- stage x transposed: xT[k][node_local] ----
    for (int i4 = tid; i4 < GEMM_TILE * 16; i4 += 512) {
        int nl = i4 >> 4;
        int k4 = (i4 & 15) * 4;
        int n = node0 + nl;
        float4 v = (n < N_NODES) ? ((const float4*)x)[(size_t)n * 16 + (i4 & 15)]
                                 : make_float4(0.f, 0.f, 0.f, 0.f);
        xT[(k4 + 0) * XT_STRIDE + nl] = v.x;
        xT[(k4 + 1) * XT_STRIDE + nl] = v.y;
        xT[(k4 + 2) * XT_STRIDE + nl] = v.z;
        xT[(k4 + 3) * XT_STRIDE + nl] = v.w;
    }
    __syncthreads();

    const int dq = (tid & 15) * 4;
    const int nq = (tid >> 4) * 4;

    float accl[4][4] = {{0.f}}, accr[4][4] = {{0.f}};

#pragma unroll 4
    for (int k = 0; k < 64; k++) {
        float4 xv = *(const float4*)&xT[k * XT_STRIDE + nq];
        float4 wl = *(const float4*)&Wls[k * 64 + dq];
        float4 wr = *(const float4*)&Wrs[k * 64 + dq];
        float xa[4] = {xv.x, xv.y, xv.z, xv.w};
        float wla[4] = {wl.x, wl.y, wl.z, wl.w};
        float wra[4] = {wr.x, wr.y, wr.z, wr.w};
#pragma unroll
        for (int i = 0; i < 4; i++)
#pragma unroll
            for (int j = 0; j < 4; j++) {
                accl[i][j] = fmaf(xa[i], wla[j], accl[i][j]);
                accr[i][j] = fmaf(xa[i], wra[j], accr[i][j]);
            }
    }

    float4 blv = *(const float4*)&bl[dq];
    float4 brv = *(const float4*)&br[dq];
    float bla[4] = {blv.x, blv.y, blv.z, blv.w};
    float bra[4] = {brv.x, brv.y, brv.z, brv.w};

#pragma unroll
    for (int i = 0; i < 4; i++) {
        int n = node0 + nq + i;
        if (n < N_NODES) {
            float4 ol, orr;
            ol.x = accl[i][0] + bla[0]; ol.y = accl[i][1] + bla[1];
            ol.z = accl[i][2] + bla[2]; ol.w = accl[i][3] + bla[3];
            orr.x = accr[i][0] + bra[0]; orr.y = accr[i][1] + bra[1];
            orr.z = accr[i][2] + bra[2]; orr.w = accr[i][3] + bra[3];
            *(float4*)&g_xl[(size_t)n * 64 + dq] = ol;
            *(float4*)&g_xr[(size_t)n * 64 + dq] = orr;
        }
    }
}

__device__ __forceinline__ float lrelu(float v) {
    return v > 0.f ? v : NEG_SLOPE * v;
}

// ---------------- K2: FUSED edge pass, 4 edges per half-warp ----------------
// Indices loaded as int4 (e0 is 4-aligned); 8 float4 gathers in flight.
// Block = 256 threads = 16 half-warps = 64 edges. 800000 % 64 == 0.
__global__ __launch_bounds__(256) void edge_kernel(
    const int* __restrict__ ei, const float* __restrict__ att)
{
    const int tid = threadIdx.x;
    const int lane = tid & 31;
    const int half = lane >> 4;
    const int l16 = lane & 15;
    const int e0 = blockIdx.x * 64 + (tid >> 5) * 8 + half * 4;

    const int4 s4 = __ldg((const int4*)&ei[e0]);
    const int4 d4 = __ldg((const int4*)&ei[N_EDGES + e0]);

    // 8 independent gathers in flight (MLP=8)
    float4 a0 = *(const float4*)&g_xl[(size_t)s4.x * 64 + l16 * 4];
    float4 a1 = *(const float4*)&g_xl[(size_t)s4.y * 64 + l16 * 4];
    float4 a2 = *(const float4*)&g_xl[(size_t)s4.z * 64 + l16 * 4];
    float4 a3 = *(const float4*)&g_xl[(size_t)s4.w * 64 + l16 * 4];
    float4 b0 = *(const float4*)&g_xr[(size_t)d4.x * 64 + l16 * 4];
    float4 b1 = *(const float4*)&g_xr[(size_t)d4.y * 64 + l16 * 4];
    float4 b2 = *(const float4*)&g_xr[(size_t)d4.z * 64 + l16 * 4];
    float4 b3 = *(const float4*)&g_xr[(size_t)d4.w * 64 + l16 * 4];
    float4 av = __ldg(&((const float4*)att)[l16]);

    float s0 = lrelu(a0.x + b0.x) * av.x + lrelu(a0.y + b0.y) * av.y +
               lrelu(a0.z + b0.z) * av.z + lrelu(a0.w + b0.w) * av.w;
    float s1 = lrelu(a1.x + b1.x) * av.x + lrelu(a1.y + b1.y) * av.y +
               lrelu(a1.z + b1.z) * av.z + lrelu(a1.w + b1.w) * av.w;
    float s2 = lrelu(a2.x + b2.x) * av.x + lrelu(a2.y + b2.y) * av.y +
               lrelu(a2.z + b2.z) * av.z + lrelu(a2.w + b2.w) * av.w;
    float s3 = lrelu(a3.x + b3.x) * av.x + lrelu(a3.y + b3.y) * av.y +
               lrelu(a3.z + b3.z) * av.z + lrelu(a3.w + b3.w) * av.w;

    s0 += __shfl_xor_sync(0xffffffffu, s0, 1);
    s0 += __shfl_xor_sync(0xffffffffu, s0, 2);
    s1 += __shfl_xor_sync(0xffffffffu, s1, 1);
    s1 += __shfl_xor_sync(0xffffffffu, s1, 2);
    s2 += __shfl_xor_sync(0xffffffffu, s2, 1);
    s2 += __shfl_xor_sync(0xffffffffu, s2, 2);
    s3 += __shfl_xor_sync(0xffffffffu, s3, 1);
    s3 += __shfl_xor_sync(0xffffffffu, s3, 2);

    const float p0 = __expf(s0);
    const float p1 = __expf(s1);
    const float p2 = __expf(s2);
    const float p3 = __expf(s3);

    float* dp0 = &g_agg[(size_t)d4.x * 64 + l16 * 4];
    asm volatile("red.global.add.v4.f32 [%0], {%1,%2,%3,%4};"
                 :: "l"(dp0), "f"(p0 * a0.x), "f"(p0 * a0.y), "f"(p0 * a0.z), "f"(p0 * a0.w)
                 : "memory");
    float* dp1 = &g_agg[(size_t)d4.y * 64 + l16 * 4];
    asm volatile("red.global.add.v4.f32 [%0], {%1,%2,%3,%4};"
                 :: "l"(dp1), "f"(p1 * a1.x), "f"(p1 * a1.y), "f"(p1 * a1.z), "f"(p1 * a1.w)
                 : "memory");
    float* dp2 = &g_agg[(size_t)d4.z * 64 + l16 * 4];
    asm volatile("red.global.add.v4.f32 [%0], {%1,%2,%3,%4};"
                 :: "l"(dp2), "f"(p2 * a2.x), "f"(p2 * a2.y), "f"(p2 * a2.z), "f"(p2 * a2.w)
                 : "memory");
    float* dp3 = &g_agg[(size_t)d4.w * 64 + l16 * 4];
    asm volatile("red.global.add.v4.f32 [%0], {%1,%2,%3,%4};"
                 :: "l"(dp3), "f"(p3 * a3.x), "f"(p3 * a3.y), "f"(p3 * a3.z), "f"(p3 * a3.w)
                 : "memory");

    if ((l16 & 3) == 0) {
        const int h = l16 >> 2;
        atomicAdd(&g_denom[(size_t)d4.x * 4 + h], p0);
        atomicAdd(&g_denom[(size_t)d4.y * 4 + h], p1);
        atomicAdd(&g_denom[(size_t)d4.z * 4 + h], p2);
        atomicAdd(&g_denom[(size_t)d4.w * 4 + h], p3);
    }
}

// ---------------- K3: normalize + residual + LayerNorm + ELU ----------------
__global__ __launch_bounds__(256) void finalize_kernel(
    const float* __restrict__ x, const float* __restrict__ bias,
    const float* __restrict__ gamma, const float* __restrict__ beta,
    float* __restrict__ out)
{
    const int tid = threadIdx.x;
    const int lane = tid & 31;
    const int half = lane >> 4;
    const int l16 = lane & 15;
    const int n = blockIdx.x * 16 + (tid >> 5) * 2 + half;

    float4 o = ((const float4*)g_agg)[n * 16 + l16];
    float den = g_denom[n * 4 + (l16 >> 2)];
    float inv_den = __fdividef(1.f, den);

    float4 xv = ((const float4*)x)[n * 16 + l16];
    float4 bv = __ldg(&((const float4*)bias)[l16]);

    float c0 = fmaf(o.x, inv_den, xv.x + bv.x);
    float c1 = fmaf(o.y, inv_den, xv.y + bv.y);
    float c2 = fmaf(o.z, inv_den, xv.z + bv.z);
    float c3 = fmaf(o.w, inv_den, xv.w + bv.w);

    float sum = c0 + c1 + c2 + c3;
    float sq = c0 * c0 + c1 * c1 + c2 * c2 + c3 * c3;
#pragma unroll
    for (int off = 8; off > 0; off >>= 1) {
        sum += __shfl_xor_sync(0xffffffff, sum, off);
        sq += __shfl_xor_sync(0xffffffff, sq, off);
    }
    float mean = sum * (1.f / 64.f);
    float var = sq * (1.f / 64.f) - mean * mean;
    float inv = rsqrtf(var + LN_EPS);

    float4 gv = __ldg(&((const float4*)gamma)[l16]);
    float4 be = __ldg(&((const float4*)beta)[l16]);

    float y0 = (c0 - mean) * inv * gv.x + be.x;
    float y1 = (c1 - mean) * inv * gv.y + be.y;
    float y2 = (c2 - mean) * inv * gv.z + be.z;
    float y3 = (c3 - mean) * inv * gv.w + be.w;
    y0 = y0 > 0.f ? y0 : expm1f(y0);
    y1 = y1 > 0.f ? y1 : expm1f(y1);
    y2 = y2 > 0.f ? y2 : expm1f(y2);
    y3 = y3 > 0.f ? y3 : expm1f(y3);

    float4 r; r.x = y0; r.y = y1; r.z = y2; r.w = y3;
    ((float4*)out)[n * 16 + l16] = r;
}

// ---------------- launch ----------------
#define GEMM_SMEM (64 * XT_STRIDE * 4 + 2 * 4096 * 4)   // 66560 B

extern "C" void kernel_launch(void* const* d_in, const int* in_sizes, int n_in,
                              void* d_out, int out_size)
{
    const float* x     = (const float*)d_in[0];
    const int*   ei    = (const int*)d_in[1];
    const float* Wl    = (const float*)d_in[2];
    const float* bl    = (const float*)d_in[3];
    const float* Wr    = (const float*)d_in[4];
    const float* br    = (const float*)d_in[5];
    const float* att   = (const float*)d_in[6];
    const float* bias  = (const float*)d_in[7];
    const float* gamma = (const float*)d_in[8];
    const float* beta  = (const float*)d_in[9];
    float* out = (float*)d_out;

    cudaFuncSetAttribute(gemm_kernel,
                         cudaFuncAttributeMaxDynamicSharedMemorySize, GEMM_SMEM);

    gemm_kernel<<<(N_NODES + GEMM_TILE - 1) / GEMM_TILE, 512, GEMM_SMEM>>>(
        x, Wl, bl, Wr, br);
    edge_kernel<<<N_EDGES / 64, 256>>>(ei, att);
    finalize_kernel<<<N_NODES / 16, 256>>>(x, bias, gamma, beta, out);
}

// round 11
// speedup vs baseline: 1.2494x; 1.0709x over previous
#include <cuda_runtime.h>
#include <cuda_fp16.h>

#define N_NODES 50000
#define N_EDGES 800000
#define NEG_SLOPE 0.2f
#define LN_EPS 1e-5f

// ---------------- scratch (no allocs allowed) ----------------
// node features in fp16: 16 x uint2 per node (each uint2 = 4 halves = 4 channels)
__device__ uint2 g_xlh[N_NODES * 16];      // xl = x@Wl + bl  (fp16 packed)
__device__ uint2 g_xrh[N_NODES * 16];      // xr = x@Wr + br  (fp16 packed)
__device__ float g_denom[N_NODES * 4];     // softmax denominators
__device__ float g_agg[N_NODES * 64];      // unnormalized aggregated messages (fp32)

__device__ __forceinline__ uint2 packh4(float a, float b, float c, float d) {
    __half2 h0 = __floats2half2_rn(a, b);
    __half2 h1 = __floats2half2_rn(c, d);
    uint2 u;
    u.x = *reinterpret_cast<unsigned int*>(&h0);
    u.y = *reinterpret_cast<unsigned int*>(&h1);
    return u;
}

__device__ __forceinline__ float4 unpackh4(uint2 u) {
    __half2 h0 = *reinterpret_cast<__half2*>(&u.x);
    __half2 h1 = *reinterpret_cast<__half2*>(&u.y);
    float2 f0 = __half22float2(h0);
    float2 f1 = __half22float2(h1);
    return make_float4(f0.x, f0.y, f1.x, f1.y);
}

// ---------------- K1: fused dual GEMM + scratch zeroing ----------------
// 256 threads, 64-node tile, 4 blocks/SM. dynamic smem 50176 B:
//   xT [64][68], Wls [64][64], Wrs [64][64]
// Each thread: 4 nodes x 4 cols x both matrices = 32 accumulators.
#define GEMM_TILE 64
#define XT_STRIDE 68
#define GEMM_SMEM ((64 * XT_STRIDE + 2 * 4096) * 4)   // 50176 B

__global__ __launch_bounds__(256, 4) void gemm_kernel(
    const float* __restrict__ x,
    const float* __restrict__ Wl, const float* __restrict__ bl,
    const float* __restrict__ Wr, const float* __restrict__ br)
{
    extern __shared__ __align__(16) float smem[];
    float* xT  = smem;                     // 64*68 floats
    float* Wls = smem + 64 * XT_STRIDE;    // 4096
    float* Wrs = Wls + 4096;               // 4096

    const int tid = threadIdx.x;
    const int node0 = blockIdx.x * GEMM_TILE;

    // ---- zero this tile's g_agg / g_denom (overlaps with staging) ----
    {
        const float4 z4 = make_float4(0.f, 0.f, 0.f, 0.f);
#pragma unroll
        for (int i = 0; i < 4; i++) {
            int q = tid + i * 256;                 // float4 idx within tile (0..1023)
            int n = node0 + (q >> 4);
            if (n < N_NODES)
                ((float4*)g_agg)[(size_t)node0 * 16 + q] = z4;
        }
        int n = node0 + (tid >> 2);
        if (n < N_NODES) g_denom[node0 * 4 + tid] = 0.f;
    }

    // ---- stage W (float4, coalesced) ----
#pragma unroll
    for (int i = tid; i < 1024; i += 256) {
        ((float4*)Wls)[i] = __ldg(&((const float4*)Wl)[i]);
        ((float4*)Wrs)[i] = __ldg(&((const float4*)Wr)[i]);
    }

    // ---- stage x transposed: xT[k][node_local] ----
    for (int i4 = tid; i4 < GEMM_TILE * 16; i4 += 256) {
        int nl = i4 >> 4;
        int k4 = (i4 & 15) * 4;
        int n = node0 + nl;
        float4 v = (n < N_NODES) ? ((const float4*)x)[(size_t)n * 16 + (i4 & 15)]
                                 : make_float4(0.f, 0.f, 0.f, 0.f);
        xT[(k4 + 0) * XT_STRIDE + nl] = v.x;
        xT[(k4 + 1) * XT_STRIDE + nl] = v.y;
        xT[(k4 + 2) * XT_STRIDE + nl] = v.z;
        xT[(k4 + 3) * XT_STRIDE + nl] = v.w;
    }
    __syncthreads();

    const int dq = (tid & 15) * 4;   // output col base
    const int nq = (tid >> 4) * 4;   // local node base

    float accl[4][4] = {{0.f}}, accr[4][4] = {{0.f}};

#pragma unroll 4
    for (int k = 0; k < 64; k++) {
        float4 xv = *(const float4*)&xT[k * XT_STRIDE + nq];
        float4 wl = *(const float4*)&Wls[k * 64 + dq];
        float4 wr = *(const float4*)&Wrs[k * 64 + dq];
        float xa[4] = {xv.x, xv.y, xv.z, xv.w};
        float wla[4] = {wl.x, wl.y, wl.z, wl.w};
        float wra[4] = {wr.x, wr.y, wr.z, wr.w};
#pragma unroll
        for (int i = 0; i < 4; i++)
#pragma unroll
            for (int j = 0; j < 4; j++) {
                accl[i][j] = fmaf(xa[i], wla[j], accl[i][j]);
                accr[i][j] = fmaf(xa[i], wra[j], accr[i][j]);
            }
    }

    float4 blv = *(const float4*)&bl[dq];
    float4 brv = *(const float4*)&br[dq];

#pragma unroll
    for (int i = 0; i < 4; i++) {
        int n = node0 + nq + i;
        if (n < N_NODES) {
            g_xlh[(size_t)n * 16 + (dq >> 2)] = packh4(
                accl[i][0] + blv.x, accl[i][1] + blv.y,
                accl[i][2] + blv.z, accl[i][3] + blv.w);
            g_xrh[(size_t)n * 16 + (dq >> 2)] = packh4(
                accr[i][0] + brv.x, accr[i][1] + brv.y,
                accr[i][2] + brv.z, accr[i][3] + brv.w);
        }
    }
}

__device__ __forceinline__ float lrelu(float v) {
    return v > 0.f ? v : NEG_SLOPE * v;
}

// ---------------- K2: FUSED edge pass, 2 edges per half-warp, fp16 gathers ----------------
// Per edge: p = exp(att . lrelu(xl[src]+xr[dst])); RED p*xl[src] -> agg (fp32),
// p -> denom. Gathers are 8 B/lane (half4). 800000 % 32 == 0.
__global__ __launch_bounds__(256) void edge_kernel(
    const int* __restrict__ ei, const float* __restrict__ att)
{
    const int tid = threadIdx.x;
    const int lane = tid & 31;
    const int half_ = lane >> 4;
    const int l16 = lane & 15;
    const int e0 = blockIdx.x * 32 + (tid >> 5) * 4 + half_ * 2;

    const int src0 = __ldg(&ei[e0]);
    const int dst0 = __ldg(&ei[N_EDGES + e0]);
    const int src1 = __ldg(&ei[e0 + 1]);
    const int dst1 = __ldg(&ei[N_EDGES + e0 + 1]);

    uint2 ua0 = __ldg(&g_xlh[(size_t)src0 * 16 + l16]);
    uint2 ub0 = __ldg(&g_xrh[(size_t)dst0 * 16 + l16]);
    uint2 ua1 = __ldg(&g_xlh[(size_t)src1 * 16 + l16]);
    uint2 ub1 = __ldg(&g_xrh[(size_t)dst1 * 16 + l16]);
    float4 av = __ldg(&((const float4*)att)[l16]);

    float4 a0 = unpackh4(ua0), b0 = unpackh4(ub0);
    float4 a1 = unpackh4(ua1), b1 = unpackh4(ub1);

    float s0 = lrelu(a0.x + b0.x) * av.x + lrelu(a0.y + b0.y) * av.y +
               lrelu(a0.z + b0.z) * av.z + lrelu(a0.w + b0.w) * av.w;
    float s1 = lrelu(a1.x + b1.x) * av.x + lrelu(a1.y + b1.y) * av.y +
               lrelu(a1.z + b1.z) * av.z + lrelu(a1.w + b1.w) * av.w;

    s0 += __shfl_xor_sync(0xffffffffu, s0, 1);
    s0 += __shfl_xor_sync(0xffffffffu, s0, 2);
    s1 += __shfl_xor_sync(0xffffffffu, s1, 1);
    s1 += __shfl_xor_sync(0xffffffffu, s1, 2);

    const float p0 = __expf(s0);
    const float p1 = __expf(s1);

    float* dp0 = &g_agg[(size_t)dst0 * 64 + l16 * 4];
    asm volatile("red.global.add.v4.f32 [%0], {%1,%2,%3,%4};"
                 :: "l"(dp0), "f"(p0 * a0.x), "f"(p0 * a0.y), "f"(p0 * a0.z), "f"(p0 * a0.w)
                 : "memory");
    float* dp1 = &g_agg[(size_t)dst1 * 64 + l16 * 4];
    asm volatile("red.global.add.v4.f32 [%0], {%1,%2,%3,%4};"
                 :: "l"(dp1), "f"(p1 * a1.x), "f"(p1 * a1.y), "f"(p1 * a1.z), "f"(p1 * a1.w)
                 : "memory");

    if ((l16 & 3) == 0) {
        const int h = l16 >> 2;
        atomicAdd(&g_denom[(size_t)dst0 * 4 + h], p0);
        atomicAdd(&g_denom[(size_t)dst1 * 4 + h], p1);
    }
}

// ---------------- K3: normalize + residual + LayerNorm + ELU ----------------
__global__ __launch_bounds__(256) void finalize_kernel(
    const float* __restrict__ x, const float* __restrict__ bias,
    const float* __restrict__ gamma, const float* __restrict__ beta,
    float* __restrict__ out)
{
    const int tid = threadIdx.x;
    const int lane = tid & 31;
    const int half_ = lane >> 4;
    const int l16 = lane & 15;
    const int n = blockIdx.x * 16 + (tid >> 5) * 2 + half_;

    float4 o = ((const float4*)g_agg)[n * 16 + l16];
    float den = g_denom[n * 4 + (l16 >> 2)];
    float inv_den = __fdividef(1.f, den);

    float4 xv = ((const float4*)x)[n * 16 + l16];
    float4 bv = __ldg(&((const float4*)bias)[l16]);

    float c0 = fmaf(o.x, inv_den, xv.x + bv.x);
    float c1 = fmaf(o.y, inv_den, xv.y + bv.y);
    float c2 = fmaf(o.z, inv_den, xv.z + bv.z);
    float c3 = fmaf(o.w, inv_den, xv.w + bv.w);

    float sum = c0 + c1 + c2 + c3;
    float sq = c0 * c0 + c1 * c1 + c2 * c2 + c3 * c3;
#pragma unroll
    for (int off = 8; off > 0; off >>= 1) {
        sum += __shfl_xor_sync(0xffffffff, sum, off);
        sq += __shfl_xor_sync(0xffffffff, sq, off);
    }
    float mean = sum * (1.f / 64.f);
    float var = sq * (1.f / 64.f) - mean * mean;
    float inv = rsqrtf(var + LN_EPS);

    float4 gv = __ldg(&((const float4*)gamma)[l16]);
    float4 be = __ldg(&((const float4*)beta)[l16]);

    float y0 = (c0 - mean) * inv * gv.x + be.x;
    float y1 = (c1 - mean) * inv * gv.y + be.y;
    float y2 = (c2 - mean) * inv * gv.z + be.z;
    float y3 = (c3 - mean) * inv * gv.w + be.w;
    y0 = y0 > 0.f ? y0 : expm1f(y0);
    y1 = y1 > 0.f ? y1 : expm1f(y1);
    y2 = y2 > 0.f ? y2 : expm1f(y2);
    y3 = y3 > 0.f ? y3 : expm1f(y3);

    float4 r; r.x = y0; r.y = y1; r.z = y2; r.w = y3;
    ((float4*)out)[n * 16 + l16] = r;
}

// ---------------- launch ----------------
extern "C" void kernel_launch(void* const* d_in, const int* in_sizes, int n_in,
                              void* d_out, int out_size)
{
    const float* x     = (const float*)d_in[0];
    const int*   ei    = (const int*)d_in[1];
    const float* Wl    = (const float*)d_in[2];
    const float* bl    = (const float*)d_in[3];
    const float* Wr    = (const float*)d_in[4];
    const float* br    = (const float*)d_in[5];
    const float* att   = (const float*)d_in[6];
    const float* bias  = (const float*)d_in[7];
    const float* gamma = (const float*)d_in[8];
    const float* beta  = (const float*)d_in[9];
    float* out = (float*)d_out;

    cudaFuncSetAttribute(gemm_kernel,
                         cudaFuncAttributeMaxDynamicSharedMemorySize, GEMM_SMEM);

    gemm_kernel<<<(N_NODES + GEMM_TILE - 1) / GEMM_TILE, 256, GEMM_SMEM>>>(
        x, Wl, bl, Wr, br);
    edge_kernel<<<N_EDGES / 32, 256>>>(ei, att);
    finalize_kernel<<<N_NODES / 16, 256>>>(x, bias, gamma, beta, out);
}